// round 3
// baseline (speedup 1.0000x reference)
#include <cuda_runtime.h>
#include <cstdint>

#define NN 100000
#define EE 1600000
#define GG 4096
#define HH 128
#define LL 4
#define DIM0 11

// ---------------- device scratch (no allocations allowed) ----------------
__device__ int    g_deg[NN];
__device__ int    g_cursor[NN];
__device__ int    g_rowptr[NN + 1];
__device__ int    g_col[EE];
__device__ float  g_wgt[EE];
__device__ float  g_dis[NN];
__device__ float4 g_h[(size_t)NN * 32];   // N x 128 as float4
__device__ float4 g_m[(size_t)NN * 32];   // N x 128 as float4
__device__ float  g_gsum[GG];
__device__ float  g_gcnt[GG];
__device__ int    g_blocksums[128];
__device__ int    g_blockoffs[128];

// ---------------- helpers ----------------
__device__ __forceinline__ float warp_sum(float v) {
#pragma unroll
    for (int o = 16; o; o >>= 1) v += __shfl_xor_sync(0xffffffffu, v, o);
    return v;
}
__device__ __forceinline__ void fma4(float4& acc, float a, const float4& w) {
    acc.x = fmaf(a, w.x, acc.x);
    acc.y = fmaf(a, w.y, acc.y);
    acc.z = fmaf(a, w.z, acc.z);
    acc.w = fmaf(a, w.w, acc.w);
}

// ---------------- setup kernels ----------------
__global__ void zero_kernel() {
    int i = blockIdx.x * blockDim.x + threadIdx.x;
    if (i < NN) { g_deg[i] = 0; g_cursor[i] = 0; }
    if (i < GG) { g_gsum[i] = 0.f; g_gcnt[i] = 0.f; }
}

__global__ void count_kernel(const int* __restrict__ dst) {
    int e = blockIdx.x * blockDim.x + threadIdx.x;
    if (e < EE) atomicAdd(&g_deg[dst[e]], 1);
}

__global__ void dis_kernel() {
    int i = blockIdx.x * blockDim.x + threadIdx.x;
    if (i < NN) g_dis[i] = rsqrtf((float)(g_deg[i] + 1));  // +1 self loop
}

// exclusive scan, 1024 elems per block
__global__ void scan1_kernel() {
    __shared__ int sh[1024];
    int tid = threadIdx.x;
    int idx = blockIdx.x * 1024 + tid;
    int v = (idx < NN) ? g_deg[idx] : 0;
    sh[tid] = v;
    __syncthreads();
#pragma unroll
    for (int off = 1; off < 1024; off <<= 1) {
        int t = (tid >= off) ? sh[tid - off] : 0;
        __syncthreads();
        sh[tid] += t;
        __syncthreads();
    }
    if (idx < NN) g_rowptr[idx] = sh[tid] - v;  // exclusive
    if (tid == 1023) g_blocksums[blockIdx.x] = sh[1023];
}

__global__ void scan2_kernel(int nblocks) {
    __shared__ int sh[128];
    int tid = threadIdx.x;
    int v = (tid < nblocks) ? g_blocksums[tid] : 0;
    sh[tid] = v;
    __syncthreads();
#pragma unroll
    for (int off = 1; off < 128; off <<= 1) {
        int t = (tid >= off) ? sh[tid - off] : 0;
        __syncthreads();
        sh[tid] += t;
        __syncthreads();
    }
    if (tid < nblocks) g_blockoffs[tid] = sh[tid] - v;  // exclusive
    if (tid == 0) g_rowptr[NN] = EE;
}

__global__ void scan3_kernel() {
    int idx = blockIdx.x * 1024 + threadIdx.x;
    if (idx < NN) g_rowptr[idx] += g_blockoffs[blockIdx.x];
}

__global__ void fill_kernel(const int* __restrict__ src,
                            const int* __restrict__ dst) {
    int e = blockIdx.x * blockDim.x + threadIdx.x;
    if (e >= EE) return;
    int s = src[e];
    int d = dst[e];
    int pos = g_rowptr[d] + atomicAdd(&g_cursor[d], 1);
    g_col[pos] = s;
    g_wgt[pos] = g_dis[s] * g_dis[d];
}

// ---------------- embed: h = relu(x @ W_embed + b_embed) ----------------
__global__ void __launch_bounds__(256) embed_kernel(const float* __restrict__ x,
                                                    const float* __restrict__ We,
                                                    const float* __restrict__ be) {
    __shared__ __align__(16) float sW[DIM0 * HH];
    for (int i = threadIdx.x; i < DIM0 * HH; i += 256) sW[i] = We[i];
    __syncthreads();
    int warp = threadIdx.x >> 5, lane = threadIdx.x & 31;
    int n = blockIdx.x * 8 + warp;
    if (n >= NN) return;
    float xv = (lane < DIM0) ? x[(size_t)n * DIM0 + lane] : 0.f;
    const float4* bv = (const float4*)be;
    float4 acc = bv[lane];
    const float4* sWv = (const float4*)sW;
#pragma unroll
    for (int k = 0; k < DIM0; k++) {
        float a = __shfl_sync(0xffffffffu, xv, k);
        fma4(acc, a, sWv[k * 32 + lane]);
    }
    acc.x = fmaxf(acc.x, 0.f); acc.y = fmaxf(acc.y, 0.f);
    acc.z = fmaxf(acc.z, 0.f); acc.w = fmaxf(acc.w, 0.f);
    g_h[(size_t)n * 32 + lane] = acc;
}

// ---------------- GEMM: m = h @ W  (N x 128 @ 128 x 128) ----------------
// block = 256 threads, 32 rows/block. K split into two 64-chunks; W-chunk
// (64x128=32KB) + A-chunk (32x64=8KB) in static smem, accumulators persist.
__global__ void __launch_bounds__(256) gemm_kernel(const float* __restrict__ W) {
    __shared__ __align__(16) float sW[64 * HH];   // 32 KB
    __shared__ __align__(16) float sA[32 * 64];   // 8 KB
    int tid = threadIdx.x;
    int warp = tid >> 5, lane = tid & 31;

    float4* sWv = (float4*)sW;
    float4* sAv = (float4*)sA;
    const float4* Wv = (const float4*)W;

    float4 z = make_float4(0.f, 0.f, 0.f, 0.f);
    float4 acc0 = z, acc1 = z, acc2 = z, acc3 = z;

#pragma unroll
    for (int p = 0; p < 2; p++) {
        if (p) __syncthreads();
        // W rows [p*64, p*64+64), all 128 cols: contiguous 2048 float4
        for (int i = tid; i < 2048; i += 256) sWv[i] = Wv[p * 2048 + i];
        // A tile: 32 rows x 16 float4 (k-chunk)
        for (int i = tid; i < 512; i += 256) {
            int r = i >> 4, q = i & 15;
            sAv[i] = g_h[((size_t)blockIdx.x * 32 + r) * 32 + p * 16 + q];
        }
        __syncthreads();

        const float* a0 = sA + warp * 4 * 64;
#pragma unroll 8
        for (int k = 0; k < 64; k++) {
            float4 wv = sWv[k * 32 + lane];
            fma4(acc0, a0[k],        wv);
            fma4(acc1, a0[64 + k],   wv);
            fma4(acc2, a0[128 + k],  wv);
            fma4(acc3, a0[192 + k],  wv);
        }
    }

    size_t row = (size_t)blockIdx.x * 32 + warp * 4;
    g_m[(row + 0) * 32 + lane] = acc0;
    g_m[(row + 1) * 32 + lane] = acc1;
    g_m[(row + 2) * 32 + lane] = acc2;
    g_m[(row + 3) * 32 + lane] = acc3;
}

// ---------------- fused aggregate + bias + LN + relu + residual ----------------
__global__ void __launch_bounds__(256) agg_kernel(const float* __restrict__ b,
                                                  const float* __restrict__ gam,
                                                  const float* __restrict__ bet) {
    int warp = threadIdx.x >> 5, lane = threadIdx.x & 31;
    int n = blockIdx.x * 8 + warp;
    if (n >= NN) return;

    float dn = g_dis[n];
    float4 acc = g_m[(size_t)n * 32 + lane];
    float sn = dn * dn;  // self loop norm
    acc.x *= sn; acc.y *= sn; acc.z *= sn; acc.w *= sn;

    int beg = g_rowptr[n], end = g_rowptr[n + 1];
    for (int e = beg; e < end; e++) {
        int s = g_col[e];
        float w = g_wgt[e];
        fma4(acc, w, g_m[(size_t)s * 32 + lane]);
    }
    float4 bb = ((const float4*)b)[lane];
    acc.x += bb.x; acc.y += bb.y; acc.z += bb.z; acc.w += bb.w;

    float mu = warp_sum(acc.x + acc.y + acc.z + acc.w) * (1.f / 128.f);
    float4 d = make_float4(acc.x - mu, acc.y - mu, acc.z - mu, acc.w - mu);
    float var = warp_sum(d.x * d.x + d.y * d.y + d.z * d.z + d.w * d.w) * (1.f / 128.f);
    float inv = rsqrtf(var + 1e-5f);

    float4 gg = ((const float4*)gam)[lane];
    float4 bt = ((const float4*)bet)[lane];
    float4 hv = g_h[(size_t)n * 32 + lane];
    float4 o;
    o.x = fmaxf(d.x * inv * gg.x + bt.x, 0.f) + hv.x;
    o.y = fmaxf(d.y * inv * gg.y + bt.y, 0.f) + hv.y;
    o.z = fmaxf(d.z * inv * gg.z + bt.z, 0.f) + hv.z;
    o.w = fmaxf(d.w * inv * gg.w + bt.w, 0.f) + hv.w;
    g_h[(size_t)n * 32 + lane] = o;
}

// ---------------- pooling: per-node dot with W_out, segment mean ----------------
__global__ void __launch_bounds__(256) pool_kernel(const int* __restrict__ batch,
                                                   const float* __restrict__ Wout) {
    int warp = threadIdx.x >> 5, lane = threadIdx.x & 31;
    int n = blockIdx.x * 8 + warp;
    if (n >= NN) return;
    float4 hv = g_h[(size_t)n * 32 + lane];
    float4 wv = ((const float4*)Wout)[lane];
    float p = warp_sum(hv.x * wv.x + hv.y * wv.y + hv.z * wv.z + hv.w * wv.w);
    if (lane == 0) {
        int gidx = batch[n];
        atomicAdd(&g_gsum[gidx], p);
        atomicAdd(&g_gcnt[gidx], 1.f);
    }
}

__global__ void out_kernel(float* __restrict__ out, const float* __restrict__ bout) {
    int gidx = blockIdx.x * blockDim.x + threadIdx.x;
    if (gidx < GG)
        out[gidx] = g_gsum[gidx] / fmaxf(g_gcnt[gidx], 1.f) + bout[0];
}

// ---------------- launch ----------------
extern "C" void kernel_launch(void* const* d_in, const int* in_sizes, int n_in,
                              void* d_out, int out_size) {
    const float* x      = (const float*)d_in[0];
    const int*   eidx   = (const int*)d_in[1];     // int32! (JAX x64 disabled)
    const int*   batch  = (const int*)d_in[2];     // int32!
    const float* Wemb   = (const float*)d_in[3];
    const float* bemb   = (const float*)d_in[4];
    const float* Wgnn   = (const float*)d_in[5];
    const float* bgnn   = (const float*)d_in[6];
    const float* gamma  = (const float*)d_in[7];
    const float* beta   = (const float*)d_in[8];
    const float* Wout   = (const float*)d_in[9];
    const float* bout   = (const float*)d_in[10];
    float* out = (float*)d_out;

    const int* src = eidx;
    const int* dst = eidx + EE;

    int nb_scan = (NN + 1023) / 1024;  // 98

    zero_kernel<<<(NN + 255) / 256, 256>>>();
    count_kernel<<<(EE + 255) / 256, 256>>>(dst);
    dis_kernel<<<(NN + 255) / 256, 256>>>();
    scan1_kernel<<<nb_scan, 1024>>>();
    scan2_kernel<<<1, 128>>>(nb_scan);
    scan3_kernel<<<nb_scan, 1024>>>();
    fill_kernel<<<(EE + 255) / 256, 256>>>(src, dst);

    embed_kernel<<<NN / 8, 256>>>(x, Wemb, bemb);

    for (int l = 0; l < LL; l++) {
        gemm_kernel<<<NN / 32, 256>>>(Wgnn + (size_t)l * HH * HH);
        agg_kernel<<<NN / 8, 256>>>(bgnn + l * HH, gamma + l * HH, beta + l * HH);
    }

    pool_kernel<<<NN / 8, 256>>>(batch, Wout);
    out_kernel<<<(GG + 255) / 256, 256>>>(out, bout);
}